// round 9
// baseline (speedup 1.0000x reference)
#include <cuda_runtime.h>
#include <math.h>

#define D 32
#define H 128
#define B 128
#define NSTEPS 8
#define NTHREADS 512
#define LOG2PI 1.8378770664093453f
#define DT 0.125f

// A[q][p] = W2[p][q] * M[q][p],  M = W1 @ W3  (trace(J) = d2^T (A d1))
__device__ float g_A[H * H];

__global__ void prep_A_kernel(const float* __restrict__ W1,
                              const float* __restrict__ W2,
                              const float* __restrict__ W3) {
    int q = blockIdx.x;
    int p = threadIdx.x;
    float m = 0.f;
#pragma unroll
    for (int i = 0; i < D; ++i)
        m = fmaf(W1[q * D + i], W3[i * H + p], m);
    g_A[q * H + p] = W2[p * H + q] * m;
}

__constant__ float c_c[6] = {0.f, 0.2f, 0.3f, 0.8f, 8.f / 9.f, 1.f};
__constant__ float c_a[6][5] = {
    {0.f, 0.f, 0.f, 0.f, 0.f},
    {0.2f, 0.f, 0.f, 0.f, 0.f},
    {3.f / 40.f, 9.f / 40.f, 0.f, 0.f, 0.f},
    {44.f / 45.f, -56.f / 15.f, 32.f / 9.f, 0.f, 0.f},
    {19372.f / 6561.f, -25360.f / 2187.f, 64448.f / 6561.f, -212.f / 729.f, 0.f},
    {9017.f / 3168.f, -355.f / 33.f, 46732.f / 5247.f, 49.f / 176.f, -5103.f / 18656.f}};
__constant__ float c_b[6] = {35.f / 384.f, 0.f, 500.f / 1113.f, 125.f / 192.f,
                             -2187.f / 6784.f, 11.f / 84.f};

__device__ __forceinline__ float tanh_fast(float x) {
    float r;
    asm("tanh.approx.f32 %0, %1;" : "=f"(r) : "f"(x));
    return r;
}

// shared memory layout (floats), 16B alignment where vector-accessed
#define OFF_HD2   0                    // float2 x 128 = 256
#define OFF_H2S   256                  // 128
#define OFF_PART  384                  // 512
#define OFF_XS    896                  // 32
#define OFF_REDW  928                  // 16
#define OFF_KS    944                  // 6*34 = 204 -> 1148
#define OFF_B3S   1148                 // 32
#define OFF_PRECS 1180                 // 32
#define OFF_XCUR  1212                 // 32
#define OFF_XACC  1244                 // 32
#define OFF_SCAL  1276                 // 4
#define OFF_W3S   1280                 // 32 * 132 = 4224 (stride-132 padded)
#define SMEM_FLOATS (OFF_W3S + 32 * 132)
#define SMEM_BYTES (SMEM_FLOATS * sizeof(float))

__global__ __launch_bounds__(NTHREADS, 1) void ode_kernel(
    const float* __restrict__ x0g, const float* __restrict__ W1g,
    const float* __restrict__ u1g, const float* __restrict__ b1g,
    const float* __restrict__ W2g, const float* __restrict__ b2g,
    const float* __restrict__ W3g, const float* __restrict__ b3g,
    const float* __restrict__ precg, float* __restrict__ out) {
    extern __shared__ float sm[];
    float2* hd2 = (float2*)(sm + OFF_HD2);
    float* h2s = sm + OFF_H2S;
    float* part = sm + OFF_PART;
    float* xs = sm + OFF_XS;
    float* redw = sm + OFF_REDW;
    float* ks = sm + OFF_KS;
    float* b3s = sm + OFF_B3S;
    float* precs = sm + OFF_PRECS;
    float* xcur = sm + OFF_XCUR;
    float* xacc = sm + OFF_XACC;
    float* scal = sm + OFF_SCAL;
    float* W3s = sm + OFF_W3S;

    const int tid = threadIdx.x;
    const int b = blockIdx.x;
    const int w = tid >> 5, lane = tid & 31;
    const int pp = lane >> 2, cc = lane & 3;   // warp-local: output pp, chunk cc
    const int p = w * 8 + pp;                  // output index in H (PA/PB)
    const int i3 = tid & 31, g3 = tid >> 5;    // PC mapping

    // ---- register-cached weights: W2/A (64) + W1 (8) only ----
    float W2r[32], Ar[32], W1r[8];
#pragma unroll
    for (int j = 0; j < 32; ++j) {
        int q = cc * 32 + j;
        W2r[j] = W2g[p * H + q];
        Ar[j] = g_A[q * H + p];
    }
#pragma unroll
    for (int j = 0; j < 8; ++j)
        W1r[j] = W1g[p * D + cc * 8 + j];
    const float u1r = u1g[p], b1r = b1g[p], b2r = b2g[p];

    // ---- W3 into padded smem (stride 132, 16B-aligned rows) ----
#pragma unroll
    for (int j = 0; j < 8; ++j)
        W3s[i3 * 132 + g3 * 8 + j] = W3g[i3 * H + g3 * 8 + j];

    // ---- ODE state into smem ----
    if (tid < 32) {
        b3s[lane] = b3g[lane];
        precs[lane] = precg[lane];
        float x0v = x0g[b * D + lane];
        xcur[lane] = x0v;
        xs[lane] = x0v;
        xacc[lane] = 0.f;
    }
    if (tid == 0) { scal[0] = 0.f; scal[1] = 0.f; }
    __syncthreads();

#pragma unroll 1
    for (int s = 0; s < NSTEPS; ++s) {
        const float t0 = (float)s * DT;
#pragma unroll 1
        for (int st = 0; st < 6; ++st) {
            const float t = fmaf(c_c[st], DT, t0);

            // ---- PA: z1 partial (8 FMA) + in-warp reduce + h1 ----
            {
                const float4* xs4 = (const float4*)xs;
                float4 xa = xs4[cc * 2];
                float4 xb = xs4[cc * 2 + 1];
                float acc = W1r[0] * xa.x;
                acc = fmaf(W1r[1], xa.y, acc);
                acc = fmaf(W1r[2], xa.z, acc);
                acc = fmaf(W1r[3], xa.w, acc);
                acc = fmaf(W1r[4], xb.x, acc);
                acc = fmaf(W1r[5], xb.y, acc);
                acc = fmaf(W1r[6], xb.z, acc);
                acc = fmaf(W1r[7], xb.w, acc);
                acc += __shfl_xor_sync(0xffffffffu, acc, 1);
                acc += __shfl_xor_sync(0xffffffffu, acc, 2);
                float z1 = fmaf(t, u1r, acc + b1r);
                float h1 = tanh_fast(z1);
                if (cc == 0) hd2[p] = make_float2(h1, 1.f - h1 * h1);
            }
            __syncthreads();

            // ---- PB: z2/av over q-chunk + in-warp reduce + h2 + trace partial ----
            {
                const float4* hd4 = ((const float4*)hd2) + cc * 16;
                float z2a = 0.f, z2b = 0.f, ava = 0.f, avb = 0.f;
#pragma unroll
                for (int j = 0; j < 16; ++j) {
                    float4 hh = hd4[j];  // {h1[2j], d1[2j], h1[2j+1], d1[2j+1]}
                    z2a = fmaf(W2r[2 * j], hh.x, z2a);
                    ava = fmaf(Ar[2 * j], hh.y, ava);
                    z2b = fmaf(W2r[2 * j + 1], hh.z, z2b);
                    avb = fmaf(Ar[2 * j + 1], hh.w, avb);
                }
                float z2 = z2a + z2b, av = ava + avb;
                z2 += __shfl_xor_sync(0xffffffffu, z2, 1);
                z2 += __shfl_xor_sync(0xffffffffu, z2, 2);
                av += __shfl_xor_sync(0xffffffffu, av, 1);
                av += __shfl_xor_sync(0xffffffffu, av, 2);
                float h2 = tanh_fast(z2 + b2r);
                if (cc == 0) h2s[p] = h2;
                float trv = (1.f - h2 * h2) * av;   // identical across cc lanes
                trv += __shfl_xor_sync(0xffffffffu, trv, 4);
                trv += __shfl_xor_sync(0xffffffffu, trv, 8);
                trv += __shfl_xor_sync(0xffffffffu, trv, 16);
                if (lane == 0) redw[w] = trv;       // sum over this warp's 8 p's
            }
            __syncthreads();

            // ---- PC: W3 partials (weights from padded smem) ----
            {
                const float4* w34 = (const float4*)(W3s + i3 * 132 + g3 * 8);
                const float4* h24 = ((const float4*)h2s) + g3 * 2;
                float4 wa = w34[0];
                float4 wb = w34[1];
                float4 ha = h24[0];
                float4 hb = h24[1];
                float o = wa.x * ha.x;
                o = fmaf(wa.y, ha.y, o);
                o = fmaf(wa.z, ha.z, o);
                o = fmaf(wa.w, ha.w, o);
                o = fmaf(wb.x, hb.x, o);
                o = fmaf(wb.y, hb.y, o);
                o = fmaf(wb.z, hb.z, o);
                o = fmaf(wb.w, hb.w, o);
                part[g3 * 32 + i3] = o;
            }
            __syncthreads();

            // ---- PD: finalize k_st + scalars + next stage x (warp 0, smem state) ----
            if (tid < 32) {
                float dx = b3s[lane];
#pragma unroll
                for (int g = 0; g < 16; ++g)
                    dx += part[g * 32 + lane];
                ks[st * 34 + lane] = dx;
                float xsv = xs[lane];
                float lp = fmaf(-0.5f * xsv, xsv, -0.5f * LOG2PI);
                float omt = 1.f - t;
                // fused KL integrand: (-0.5*omt^2*lp + 0.5*omt*(1+t)*prec*x) * dx
                float contrib = fmaf(-0.5f * omt * omt, lp,
                                     0.5f * omt * (1.f + t) * precs[lane] * xsv) * dx;
                float trp = (lane < 16) ? redw[lane] : 0.f;
#pragma unroll
                for (int off = 16; off; off >>= 1) {
                    contrib += __shfl_xor_sync(0xffffffffu, contrib, off);
                    trp += __shfl_xor_sync(0xffffffffu, trp, off);
                }
                float bst = DT * c_b[st];
                float xa_new = fmaf(bst, dx, xacc[lane]);
                if (lane == 0) {
                    float dlogp = -trp;
                    scal[0] = fmaf(bst, dlogp, scal[0]);
                    scal[1] = fmaf(bst, contrib + omt * dlogp, scal[1]);
                }
                float xn;
                if (st < 5) {
                    xn = xcur[lane];
                    for (int j = 0; j <= st; ++j)
                        xn = fmaf(DT * c_a[st + 1][j], ks[j * 34 + lane], xn);
                    xacc[lane] = xa_new;
                } else {
                    xn = xcur[lane] + xa_new;
                    xcur[lane] = xn;
                    xacc[lane] = 0.f;
                }
                xs[lane] = xn;
            }
            __syncthreads();
        }
    }

    // ---- outputs: z [B*D], logp [B], kl [B] ----
    if (tid < 32) {
        out[b * D + lane] = xcur[lane];
        float x0v = x0g[b * D + lane];
        float lp = fmaf(-0.5f * x0v, x0v, -0.5f * LOG2PI);
#pragma unroll
        for (int off = 16; off; off >>= 1)
            lp += __shfl_xor_sync(0xffffffffu, lp, off);
        if (lane == 0) {
            out[B * D + b] = lp + scal[0];
            out[B * D + B + b] = scal[1];
        }
    }
}

extern "C" void kernel_launch(void* const* d_in, const int* in_sizes, int n_in,
                              void* d_out, int out_size) {
    const float* x0 = (const float*)d_in[0];
    const float* W1 = (const float*)d_in[1];
    const float* u1 = (const float*)d_in[2];
    const float* b1 = (const float*)d_in[3];
    const float* W2 = (const float*)d_in[4];
    const float* b2 = (const float*)d_in[5];
    const float* W3 = (const float*)d_in[6];
    const float* b3 = (const float*)d_in[7];
    const float* prec = (const float*)d_in[8];
    float* out = (float*)d_out;

    prep_A_kernel<<<H, H>>>(W1, W2, W3);
    ode_kernel<<<B, NTHREADS, SMEM_BYTES>>>(x0, W1, u1, b1, W2, b2, W3, b3, prec, out);
}

// round 10
// speedup vs baseline: 2.3322x; 2.3322x over previous
#include <cuda_runtime.h>
#include <math.h>

#define D 32
#define H 128
#define B 128
#define NSTEPS 8
#define NTHREADS 512
#define LOG2PI 1.8378770664093453f
#define DT 0.125f

// A[q][p] = W2[p][q] * M[q][p],  M = W1 @ W3  (trace(J) = d2^T (A d1))
__device__ float g_A[H * H];

__global__ void prep_A_kernel(const float* __restrict__ W1,
                              const float* __restrict__ W2,
                              const float* __restrict__ W3) {
    int q = blockIdx.x;
    int p = threadIdx.x;
    float m = 0.f;
#pragma unroll
    for (int i = 0; i < D; ++i)
        m = fmaf(W1[q * D + i], W3[i * H + p], m);
    g_A[q * H + p] = W2[p * H + q] * m;
}

__constant__ float c_c[6] = {0.f, 0.2f, 0.3f, 0.8f, 8.f / 9.f, 1.f};
__constant__ float c_a[6][5] = {
    {0.f, 0.f, 0.f, 0.f, 0.f},
    {0.2f, 0.f, 0.f, 0.f, 0.f},
    {3.f / 40.f, 9.f / 40.f, 0.f, 0.f, 0.f},
    {44.f / 45.f, -56.f / 15.f, 32.f / 9.f, 0.f, 0.f},
    {19372.f / 6561.f, -25360.f / 2187.f, 64448.f / 6561.f, -212.f / 729.f, 0.f},
    {9017.f / 3168.f, -355.f / 33.f, 46732.f / 5247.f, 49.f / 176.f, -5103.f / 18656.f}};
__constant__ float c_b[6] = {35.f / 384.f, 0.f, 500.f / 1113.f, 125.f / 192.f,
                             -2187.f / 6784.f, 11.f / 84.f};

__device__ __forceinline__ float tanh_fast(float x) {
    float r;
    asm("tanh.approx.f32 %0, %1;" : "=f"(r) : "f"(x));
    return r;
}

// shared memory layout (floats), 16B alignment where vector-accessed
#define OFF_Z1PART 0                    // 512
#define OFF_PART2  512                  // float2 x 512 = 1024
#define OFF_PART   1536                 // 512
#define OFF_HD2    2048                 // float2 x 128 = 256
#define OFF_H2S    2304                 // 128
#define OFF_XS     2432                 // 32
#define OFF_REDW   2464                 // 16
#define OFF_KS     2480                 // 6*34 = 204
#define OFF_B3S    2684                 // 32
#define OFF_PRECS  2716                 // 32
#define OFF_XCUR   2748                 // 32
#define OFF_XACC   2780                 // 32
#define OFF_SCAL   2812                 // 4
#define SMEM_FLOATS (OFF_SCAL + 4)
#define SMEM_BYTES (SMEM_FLOATS * sizeof(float))

__global__ __launch_bounds__(NTHREADS, 1) void ode_kernel(
    const float* __restrict__ x0g, const float* __restrict__ W1g,
    const float* __restrict__ u1g, const float* __restrict__ b1g,
    const float* __restrict__ W2g, const float* __restrict__ b2g,
    const float* __restrict__ W3g, const float* __restrict__ b3g,
    const float* __restrict__ precg, float* __restrict__ out) {
    extern __shared__ float sm[];
    float* z1part = sm + OFF_Z1PART;
    float2* part2 = (float2*)(sm + OFF_PART2);
    float* part = sm + OFF_PART;
    float2* hd2 = (float2*)(sm + OFF_HD2);
    float* h2s = sm + OFF_H2S;
    float* xs = sm + OFF_XS;
    float* redw = sm + OFF_REDW;
    float* ks = sm + OFF_KS;
    float* b3s = sm + OFF_B3S;
    float* precs = sm + OFF_PRECS;
    float* xcur = sm + OFF_XCUR;
    float* xacc = sm + OFF_XACC;
    float* scal = sm + OFF_SCAL;

    const int tid = threadIdx.x;
    const int b = blockIdx.x;
    const int lane = tid & 31;
    const int p = tid & 127;     // output index within H
    const int c = tid >> 7;      // chunk 0..3 over q/k reduction dim
    const int i3 = tid & 31;     // W3 output index
    const int g3 = tid >> 5;     // W3 chunk 0..15

    // ---- register-cached weights (loaded once), exactly as the 68us baseline ----
    float W2r[32], Ar[32], W1r[8], W3r[8];
#pragma unroll
    for (int j = 0; j < 32; ++j) {
        int q = c * 32 + j;
        W2r[j] = W2g[p * H + q];   // W2[p][q]
        Ar[j] = g_A[q * H + p];    // A[q][p]
    }
#pragma unroll
    for (int j = 0; j < 8; ++j)
        W1r[j] = W1g[p * D + c * 8 + j];   // W1[p][k]
#pragma unroll
    for (int j = 0; j < 8; ++j)
        W3r[j] = W3g[i3 * H + g3 * 8 + j]; // W3[i][p]
    const float u1r = u1g[p], b1r = b1g[p], b2r = b2g[p];

    // ---- ODE state into smem ----
    if (tid < 32) {
        b3s[lane] = b3g[lane];
        precs[lane] = precg[lane];
        float x0v = x0g[b * D + lane];
        xcur[lane] = x0v;
        xs[lane] = x0v;
        xacc[lane] = 0.f;
    }
    if (tid == 0) { scal[0] = 0.f; scal[1] = 0.f; }
    __syncthreads();

#pragma unroll 1
    for (int s = 0; s < NSTEPS; ++s) {
        const float t0 = (float)s * DT;
#pragma unroll 1
        for (int st = 0; st < 6; ++st) {
            const float t = fmaf(c_c[st], DT, t0);

            // ---- P1: z1 partials: thread (c,p), k-range 8 ----
            {
                float acc = 0.f;
#pragma unroll
                for (int j = 0; j < 8; ++j)
                    acc = fmaf(W1r[j], xs[c * 8 + j], acc);
                z1part[c * 128 + p] = acc;
            }
            __syncthreads();

            // ---- P2: h1 finalize (first 128 threads) ----
            if (tid < H) {
                float z1 = z1part[tid] + z1part[128 + tid] + z1part[256 + tid] +
                           z1part[384 + tid];
                z1 = fmaf(t, u1r, z1 + b1r);
                float h1 = tanh_fast(z1);
                hd2[tid] = make_float2(h1, 1.f - h1 * h1);
            }
            __syncthreads();

            // ---- P3: hot loop, z2/av partials (float4 broadcast loads) ----
            {
                float z2a = 0.f, z2b = 0.f, ava = 0.f, avb = 0.f;
                const float4* hd4 = reinterpret_cast<const float4*>(hd2) + c * 16;
#pragma unroll
                for (int j = 0; j < 16; ++j) {
                    float4 hh = hd4[j];   // {h1[2j], d1[2j], h1[2j+1], d1[2j+1]}
                    z2a = fmaf(W2r[2 * j], hh.x, z2a);
                    ava = fmaf(Ar[2 * j], hh.y, ava);
                    z2b = fmaf(W2r[2 * j + 1], hh.z, z2b);
                    avb = fmaf(Ar[2 * j + 1], hh.w, avb);
                }
                part2[c * 128 + p] = make_float2(z2a + z2b, ava + avb);
            }
            __syncthreads();

            // ---- P4: h2 finalize (first 128 threads) + per-warp trace partial ----
            if (tid < H) {
                float2 a0 = part2[tid];
                float2 a1 = part2[128 + tid];
                float2 a2 = part2[256 + tid];
                float2 a3 = part2[384 + tid];
                float z2 = a0.x + a1.x + a2.x + a3.x + b2r;
                float av = a0.y + a1.y + a2.y + a3.y;
                float h2 = tanh_fast(z2);
                h2s[tid] = h2;
                float trv = (1.f - h2 * h2) * av;
#pragma unroll
                for (int off = 16; off; off >>= 1)
                    trv += __shfl_xor_sync(0xffffffffu, trv, off);
                if (lane == 0) redw[tid >> 5] = trv;   // warps 0..3
            }
            __syncthreads();

            // ---- P5: W3 partials (all threads) ----
            {
                float o = 0.f;
#pragma unroll
                for (int j = 0; j < 8; ++j)
                    o = fmaf(W3r[j], h2s[g3 * 8 + j], o);
                part[g3 * 32 + i3] = o;
            }
            __syncthreads();

            // ---- P6: finalize k_st + scalars + next stage x (warp 0) ----
            if (tid < 32) {
                float dx = b3s[lane];
#pragma unroll
                for (int g = 0; g < 16; ++g)
                    dx += part[g * 32 + lane];
                ks[st * 34 + lane] = dx;
                float xsv = xs[lane];
                float lp = fmaf(-0.5f * xsv, xsv, -0.5f * LOG2PI);
                float omt = 1.f - t;
                // fused KL integrand: (-0.5*omt^2*lp + 0.5*omt*(1+t)*prec*x) * dx
                float contrib = fmaf(-0.5f * omt * omt, lp,
                                     0.5f * omt * (1.f + t) * precs[lane] * xsv) * dx;
                float trp = (lane < 4) ? redw[lane] : 0.f;
#pragma unroll
                for (int off = 16; off; off >>= 1) {
                    contrib += __shfl_xor_sync(0xffffffffu, contrib, off);
                    trp += __shfl_xor_sync(0xffffffffu, trp, off);
                }
                float bst = DT * c_b[st];
                float xa_new = fmaf(bst, dx, xacc[lane]);
                if (lane == 0) {
                    float dlogp = -trp;
                    scal[0] = fmaf(bst, dlogp, scal[0]);
                    scal[1] = fmaf(bst, contrib + omt * dlogp, scal[1]);
                }
                float xn;
                if (st < 5) {
                    xn = xcur[lane];
                    for (int j = 0; j <= st; ++j)
                        xn = fmaf(DT * c_a[st + 1][j], ks[j * 34 + lane], xn);
                    xacc[lane] = xa_new;
                } else {
                    xn = xcur[lane] + xa_new;
                    xcur[lane] = xn;
                    xacc[lane] = 0.f;
                }
                xs[lane] = xn;
            }
            __syncthreads();
        }
    }

    // ---- outputs: z [B*D], logp [B], kl [B] ----
    if (tid < 32) {
        out[b * D + lane] = xcur[lane];
        float x0v = x0g[b * D + lane];
        float lp = fmaf(-0.5f * x0v, x0v, -0.5f * LOG2PI);
#pragma unroll
        for (int off = 16; off; off >>= 1)
            lp += __shfl_xor_sync(0xffffffffu, lp, off);
        if (lane == 0) {
            out[B * D + b] = lp + scal[0];
            out[B * D + B + b] = scal[1];
        }
    }
}

extern "C" void kernel_launch(void* const* d_in, const int* in_sizes, int n_in,
                              void* d_out, int out_size) {
    const float* x0 = (const float*)d_in[0];
    const float* W1 = (const float*)d_in[1];
    const float* u1 = (const float*)d_in[2];
    const float* b1 = (const float*)d_in[3];
    const float* W2 = (const float*)d_in[4];
    const float* b2 = (const float*)d_in[5];
    const float* W3 = (const float*)d_in[6];
    const float* b3 = (const float*)d_in[7];
    const float* prec = (const float*)d_in[8];
    float* out = (float*)d_out;

    prep_A_kernel<<<H, H>>>(W1, W2, W3);
    ode_kernel<<<B, NTHREADS, SMEM_BYTES>>>(x0, W1, u1, b1, W2, b2, W3, b3, prec, out);
}

// round 11
// speedup vs baseline: 2.4093x; 1.0331x over previous
#include <cuda_runtime.h>
#include <math.h>

#define D 32
#define H 128
#define B 128
#define NSTEPS 8
#define NTHREADS 512
#define LOG2PI 1.8378770664093453f
#define DT 0.125f

// A[q][p] = W2[p][q] * M[q][p],  M = W1 @ W3  (trace(J) = d2^T (A d1))
__device__ float g_A[H * H];

__global__ void prep_A_kernel(const float* __restrict__ W1,
                              const float* __restrict__ W2,
                              const float* __restrict__ W3) {
    int q = blockIdx.x;
    int p = threadIdx.x;
    float m = 0.f;
#pragma unroll
    for (int i = 0; i < D; ++i)
        m = fmaf(W1[q * D + i], W3[i * H + p], m);
    g_A[q * H + p] = W2[p * H + q] * m;
}

__constant__ float c_c[6] = {0.f, 0.2f, 0.3f, 0.8f, 8.f / 9.f, 1.f};
__constant__ float c_a[6][5] = {
    {0.f, 0.f, 0.f, 0.f, 0.f},
    {0.2f, 0.f, 0.f, 0.f, 0.f},
    {3.f / 40.f, 9.f / 40.f, 0.f, 0.f, 0.f},
    {44.f / 45.f, -56.f / 15.f, 32.f / 9.f, 0.f, 0.f},
    {19372.f / 6561.f, -25360.f / 2187.f, 64448.f / 6561.f, -212.f / 729.f, 0.f},
    {9017.f / 3168.f, -355.f / 33.f, 46732.f / 5247.f, 49.f / 176.f, -5103.f / 18656.f}};
__constant__ float c_b[6] = {35.f / 384.f, 0.f, 500.f / 1113.f, 125.f / 192.f,
                             -2187.f / 6784.f, 11.f / 84.f};

__device__ __forceinline__ float tanh_fast(float x) {
    float r;
    asm("tanh.approx.f32 %0, %1;" : "=f"(r) : "f"(x));
    return r;
}

// shared memory layout (floats), 16B alignment where vector-accessed
#define OFF_PART2  0                    // float2 x 512 = 1024
#define OFF_PART   1024                 // 512
#define OFF_HD2    1536                 // float2 x 128 = 256
#define OFF_H2S    1792                 // 128
#define OFF_TRS    1920                 // 128
#define OFF_XS     2048                 // 32
#define OFF_KS     2080                 // 6*34 = 204
#define OFF_B3S    2284                 // 32
#define OFF_PRECS  2316                 // 32
#define OFF_XCUR   2348                 // 32
#define OFF_XACC   2380                 // 32
#define OFF_SCAL   2412                 // 4
#define OFF_W1C    2416                 // 32*129 = 4128
#define SMEM_FLOATS (OFF_W1C + 32 * 129)
#define SMEM_BYTES (SMEM_FLOATS * sizeof(float))

__global__ __launch_bounds__(NTHREADS, 1) void ode_kernel(
    const float* __restrict__ x0g, const float* __restrict__ W1g,
    const float* __restrict__ u1g, const float* __restrict__ b1g,
    const float* __restrict__ W2g, const float* __restrict__ b2g,
    const float* __restrict__ W3g, const float* __restrict__ b3g,
    const float* __restrict__ precg, float* __restrict__ out) {
    extern __shared__ float sm[];
    float2* part2 = (float2*)(sm + OFF_PART2);
    float* part = sm + OFF_PART;
    float2* hd2 = (float2*)(sm + OFF_HD2);
    float* h2s = sm + OFF_H2S;
    float* trs = sm + OFF_TRS;
    float* xs = sm + OFF_XS;
    float* ks = sm + OFF_KS;
    float* b3s = sm + OFF_B3S;
    float* precs = sm + OFF_PRECS;
    float* xcur = sm + OFF_XCUR;
    float* xacc = sm + OFF_XACC;
    float* scal = sm + OFF_SCAL;
    float* W1c = sm + OFF_W1C;

    const int tid = threadIdx.x;
    const int b = blockIdx.x;
    const int lane = tid & 31;
    const int p = tid & 127;     // output index within H
    const int c = tid >> 7;      // chunk 0..3 over q reduction dim (P3)
    const int i3 = tid & 31;     // W3 output index
    const int g3 = tid >> 5;     // W3 chunk 0..15

    // ---- register-cached weights: W2/A (64) + W3 (8) ----
    float W2r[32], Ar[32], W3r[8];
#pragma unroll
    for (int j = 0; j < 32; ++j) {
        int q = c * 32 + j;
        W2r[j] = W2g[p * H + q];   // W2[p][q]
        Ar[j] = g_A[q * H + p];    // A[q][p]
    }
#pragma unroll
    for (int j = 0; j < 8; ++j)
        W3r[j] = W3g[i3 * H + g3 * 8 + j]; // W3[i][p]
    const float u1r = u1g[p], b1r = b1g[p], b2r = b2g[p];

    // ---- W1 into padded smem: W1c[k*129 + p] = W1[p][k] ----
    {
        int idx = tid * 8;
        int pr = idx >> 5, kr = idx & 31;
#pragma unroll
        for (int j = 0; j < 8; ++j)
            W1c[(kr + j) * 129 + pr] = W1g[pr * D + kr + j];
    }

    // ---- ODE state into smem ----
    if (tid < 32) {
        b3s[lane] = b3g[lane];
        precs[lane] = precg[lane];
        float x0v = x0g[b * D + lane];
        xcur[lane] = x0v;
        xs[lane] = x0v;
        xacc[lane] = 0.f;
    }
    if (tid == 0) { scal[0] = 0.f; scal[1] = 0.f; }
    __syncthreads();

#pragma unroll 1
    for (int s = 0; s < NSTEPS; ++s) {
        const float t0 = (float)s * DT;
#pragma unroll 1
        for (int st = 0; st < 6; ++st) {
            const float t = fmaf(c_c[st], DT, t0);

            // ---- PA: full z1 + h1 (first 128 threads, W1 from smem) ----
            if (tid < H) {
                const float4* xs4 = (const float4*)xs;
                float acc = 0.f;
#pragma unroll
                for (int k4 = 0; k4 < 8; ++k4) {
                    float4 xv = xs4[k4];
                    int kb = k4 * 4;
                    acc = fmaf(W1c[kb * 129 + tid], xv.x, acc);
                    acc = fmaf(W1c[(kb + 1) * 129 + tid], xv.y, acc);
                    acc = fmaf(W1c[(kb + 2) * 129 + tid], xv.z, acc);
                    acc = fmaf(W1c[(kb + 3) * 129 + tid], xv.w, acc);
                }
                float z1 = fmaf(t, u1r, acc + b1r);
                float h1 = tanh_fast(z1);
                hd2[tid] = make_float2(h1, 1.f - h1 * h1);
            }
            __syncthreads();

            // ---- P3: hot loop, z2/av partials (float4 broadcast loads) ----
            {
                float z2a = 0.f, z2b = 0.f, ava = 0.f, avb = 0.f;
                const float4* hd4 = reinterpret_cast<const float4*>(hd2) + c * 16;
#pragma unroll
                for (int j = 0; j < 16; ++j) {
                    float4 hh = hd4[j];   // {h1[2j], d1[2j], h1[2j+1], d1[2j+1]}
                    z2a = fmaf(W2r[2 * j], hh.x, z2a);
                    ava = fmaf(Ar[2 * j], hh.y, ava);
                    z2b = fmaf(W2r[2 * j + 1], hh.z, z2b);
                    avb = fmaf(Ar[2 * j + 1], hh.w, avb);
                }
                part2[c * 128 + p] = make_float2(z2a + z2b, ava + avb);
            }
            __syncthreads();

            // ---- P4: h2 finalize + trace term to smem (no shfl chain) ----
            if (tid < H) {
                float2 a0 = part2[tid];
                float2 a1 = part2[128 + tid];
                float2 a2 = part2[256 + tid];
                float2 a3 = part2[384 + tid];
                float z2 = a0.x + a1.x + a2.x + a3.x + b2r;
                float av = a0.y + a1.y + a2.y + a3.y;
                float h2 = tanh_fast(z2);
                h2s[tid] = h2;
                trs[tid] = (1.f - h2 * h2) * av;
            }
            __syncthreads();

            // ---- P5: W3 partials (all threads) ----
            {
                float o = 0.f;
#pragma unroll
                for (int j = 0; j < 8; ++j)
                    o = fmaf(W3r[j], h2s[g3 * 8 + j], o);
                part[g3 * 32 + i3] = o;
            }
            __syncthreads();

            // ---- P6: finalize k_st + scalars + next stage x (warp 0) ----
            if (tid < 32) {
                float dx = b3s[lane];
#pragma unroll
                for (int g = 0; g < 16; ++g)
                    dx += part[g * 32 + lane];
                ks[st * 34 + lane] = dx;
                float xsv = xs[lane];
                float lp = fmaf(-0.5f * xsv, xsv, -0.5f * LOG2PI);
                float omt = 1.f - t;
                // fused KL integrand: (-0.5*omt^2*lp + 0.5*omt*(1+t)*prec*x) * dx
                float contrib = fmaf(-0.5f * omt * omt, lp,
                                     0.5f * omt * (1.f + t) * precs[lane] * xsv) * dx;
                float trp = trs[lane] + trs[lane + 32] + trs[lane + 64] + trs[lane + 96];
#pragma unroll
                for (int off = 16; off; off >>= 1) {
                    contrib += __shfl_xor_sync(0xffffffffu, contrib, off);
                    trp += __shfl_xor_sync(0xffffffffu, trp, off);
                }
                float bst = DT * c_b[st];
                float xa_new = fmaf(bst, dx, xacc[lane]);
                if (lane == 0) {
                    float dlogp = -trp;
                    scal[0] = fmaf(bst, dlogp, scal[0]);
                    scal[1] = fmaf(bst, contrib + omt * dlogp, scal[1]);
                }
                float xn;
                if (st < 5) {
                    xn = xcur[lane];
                    for (int j = 0; j <= st; ++j)
                        xn = fmaf(DT * c_a[st + 1][j], ks[j * 34 + lane], xn);
                    xacc[lane] = xa_new;
                } else {
                    xn = xcur[lane] + xa_new;
                    xcur[lane] = xn;
                    xacc[lane] = 0.f;
                }
                xs[lane] = xn;
            }
            __syncthreads();
        }
    }

    // ---- outputs: z [B*D], logp [B], kl [B] ----
    if (tid < 32) {
        out[b * D + lane] = xcur[lane];
        float x0v = x0g[b * D + lane];
        float lp = fmaf(-0.5f * x0v, x0v, -0.5f * LOG2PI);
#pragma unroll
        for (int off = 16; off; off >>= 1)
            lp += __shfl_xor_sync(0xffffffffu, lp, off);
        if (lane == 0) {
            out[B * D + b] = lp + scal[0];
            out[B * D + B + b] = scal[1];
        }
    }
}

extern "C" void kernel_launch(void* const* d_in, const int* in_sizes, int n_in,
                              void* d_out, int out_size) {
    const float* x0 = (const float*)d_in[0];
    const float* W1 = (const float*)d_in[1];
    const float* u1 = (const float*)d_in[2];
    const float* b1 = (const float*)d_in[3];
    const float* W2 = (const float*)d_in[4];
    const float* b2 = (const float*)d_in[5];
    const float* W3 = (const float*)d_in[6];
    const float* b3 = (const float*)d_in[7];
    const float* prec = (const float*)d_in[8];
    float* out = (float*)d_out;

    prep_A_kernel<<<H, H>>>(W1, W2, W3);
    ode_kernel<<<B, NTHREADS, SMEM_BYTES>>>(x0, W1, u1, b1, W2, b2, W3, b3, prec, out);
}